// round 15
// baseline (speedup 1.0000x reference)
#include <cuda_runtime.h>
#include <stdint.h>

#define NFULL 512
#define DIMF  64
#define H1    260
#define MD    17
#define CHID  68
#define NMAX  460
#define N0 460
#define N1 358
#define N2 307
#define NTOT 1125
// edge grid: gx {16,12,11} x nspl {9,7,6} -> {144,84,66} = 294 blocks (one wave @2/SM)
#define EGRID 294
#define RPB   30   // rows per block (10 warps x 3 rows)
#define ETHR  320

typedef unsigned long long ull;

// ---------------- device scratch (per-pool batched) ----------------
__device__ uint32_t g_ugbits[NFULL*16];
__device__ uint32_t g_ug2bits[NFULL*16];
__device__ float    g_scores[3*NFULL];
__device__ int      g_idx[3*NFULL];
__device__ uint32_t g_gsub[3*NMAX*16];
__device__ float    g_hc[3*NMAX*DIMF];
__device__ float    g_cA[3*NMAX*3];
__device__ float    g_cB[3*NMAX*3];
__device__ float    g_Arow[3*NMAX*H1];
__device__ float    g_Brow[3*NMAX*H1];
__device__ float    g_mi[3*NMAX*MD];

// ---------------- helpers ----------------
__device__ __forceinline__ float ex2a(float x){ float y; asm("ex2.approx.ftz.f32 %0, %1;" : "=f"(y) : "f"(x)); return y; }
__device__ __forceinline__ float rcpa(float x){ float y; asm("rcp.approx.ftz.f32 %0, %1;" : "=f"(y) : "f"(x)); return y; }
__device__ __forceinline__ float tanha(float x){ float y; asm("tanh.approx.f32 %0, %1;" : "=f"(y) : "f"(x)); return y; }
__device__ __forceinline__ float siluf(float x){
    return x * rcpa(1.0f + ex2a(-1.4426950408889634f * x));
}
__device__ __forceinline__ float silut(float x){
    float h = 0.5f * x;
    return fmaf(h, tanha(h), h);
}
__device__ __forceinline__ float sigf(float x){
    return rcpa(1.0f + ex2a(-1.4426950408889634f * x));
}
__device__ __forceinline__ ull pk2(float lo, float hi){
    ull r; asm("mov.b64 %0, {%1,%2};" : "=l"(r) : "r"(__float_as_uint(lo)), "r"(__float_as_uint(hi))); return r;
}
__device__ __forceinline__ ull dup2(float v){
    ull r; asm("mov.b64 %0, {%1,%1};" : "=l"(r) : "r"(__float_as_uint(v))); return r;
}
__device__ __forceinline__ void unpk(ull v, float& lo, float& hi){
    unsigned a, b;
    asm("mov.b64 {%0,%1}, %2;" : "=r"(a), "=r"(b) : "l"(v));
    lo = __uint_as_float(a); hi = __uint_as_float(b);
}
__device__ __forceinline__ ull fma2(ull a, ull b, ull c){
    ull d; asm("fma.rn.f32x2 %0, %1, %2, %3;" : "=l"(d) : "l"(a), "l"(b), "l"(c)); return d;
}
__device__ __forceinline__ ull add2(ull a, ull b){
    ull d; asm("add.rn.f32x2 %0, %1, %2;" : "=l"(d) : "l"(a), "l"(b)); return d;
}
__device__ __forceinline__ ull mul2(ull a, ull b){
    ull d; asm("mul.rn.f32x2 %0, %1, %2;" : "=l"(d) : "l"(a), "l"(b)); return d;
}
// packed silu via tanh: silu(x) = h + h*tanh(h), h = x/2
__device__ __forceinline__ ull silu2t(ull x, ull HALF2){
    ull h = mul2(x, HALF2);
    float h0, h1; unpk(h, h0, h1);
    ull t = pk2(tanha(h0), tanha(h1));
    return fma2(h, t, h);
}
__device__ __forceinline__ ull shflx2(ull v, int off){
    float lo, hi; unpk(v, lo, hi);
    lo = __shfl_xor_sync(0xffffffffu, lo, off);
    hi = __shfl_xor_sync(0xffffffffu, hi, off);
    return pk2(lo, hi);
}
__device__ __forceinline__ void pool_of(int bid, int& p, int& i, int& n){
    if (bid < N0){ p = 0; i = bid; n = N0; }
    else if (bid < N0+N1){ p = 1; i = bid - N0; n = N1; }
    else { p = 2; i = bid - N0 - N1; n = N2; }
}

// packed coor MLP over one ull-me vector (rows packed in the 2 lanes)
__device__ __forceinline__ ull coor_mlp2(const ull (&me)[MD],
        const float* __restrict__ wc1d, const ull* __restrict__ bc1u,
        const ull* __restrict__ wc2u, ull cw0, ull HALF2){
    ull cw = cw0;
    #pragma unroll 2
    for (int h2 = 0; h2 < CHID/2; h2++){
        ull a0 = bc1u[2*h2], a1 = bc1u[2*h2+1];
        #pragma unroll
        for (int t = 0; t < MD; t++){
            ulonglong2 wwp = ((const ulonglong2*)(wc1d + t*136))[h2];
            a0 = fma2(me[t], wwp.x, a0);
            a1 = fma2(me[t], wwp.y, a1);
        }
        a0 = silu2t(a0, HALF2); a1 = silu2t(a1, HALF2);
        cw = fma2(a0, wc2u[2*h2],   cw);
        cw = fma2(a1, wc2u[2*h2+1], cw);
    }
    return cw;
}

// ---------------- launch 0: adjacency bits + pool scores ----------------
__global__ void k_ugbits_scores(const float* __restrict__ edge, const float* __restrict__ feat,
                                const float* __restrict__ wp, const float* __restrict__ bp){
    int a = blockIdx.x, tid = threadIdx.x, lane = tid & 31, w = tid >> 5;
    bool b = edge[a*NFULL + tid] != 0.0f;
    unsigned m = __ballot_sync(0xffffffffu, b);
    if (lane == 0) g_ugbits[a*16 + w] = m;
    if (w < 3){
        float v = feat[a*DIMF + lane]*wp[w*DIMF + lane]
                + feat[a*DIMF + 32 + lane]*wp[w*DIMF + 32 + lane];
        for (int off = 16; off; off >>= 1) v += __shfl_xor_sync(0xffffffffu, v, off);
        if (lane == 0) g_scores[w*NFULL + a] = sigf(v + bp[w]);
    }
}

// ---------------- launch 1: fused ug2 (y=0, + zero out) + rank (y=1..3) ----------------
__global__ void k_ug2rank(float* out){
    int tid = threadIdx.x, lane = tid & 31, w = tid >> 5;
    int a = blockIdx.x;
    if (blockIdx.y == 0){
        if (tid < 64) out[a*64 + tid] = 0.0f;
        __shared__ uint32_t row[16];
        __shared__ uint32_t accs[4][16];
        if (tid < 16) row[tid] = g_ugbits[a*16 + tid];
        __syncthreads();
        uint32_t acc = 0;
        int c0 = w*128;
        for (int c = c0; c < c0 + 128; c++){
            if ((row[c>>5] >> (c&31)) & 1u){
                if (lane < 16) acc |= g_ugbits[c*16 + lane];
            }
        }
        if (lane < 16) accs[w][lane] = acc;
        __syncthreads();
        if (tid < 16)
            g_ug2bits[a*16 + tid] = accs[0][tid] | accs[1][tid] | accs[2][tid] | accs[3][tid];
    } else {
        __shared__ int ired[4];
        int p = blockIdx.y - 1;
        int kcnt = (p == 0) ? N0 : (p == 1) ? N1 : N2;
        const float* sc = g_scores + p*NFULL;
        float s = sc[a];
        int r = 0;
        for (int b = tid; b < NFULL; b += 128){
            float sb = sc[b];
            r += (sb > s) || (sb == s && b < a);
        }
        for (int off = 16; off; off >>= 1) r += __shfl_xor_sync(0xffffffffu, r, off);
        if (lane == 0) ired[w] = r;
        __syncthreads();
        if (tid == 0){
            int rt = ired[0] + ired[1] + ired[2] + ired[3];
            if (rt < kcnt) g_idx[p*NFULL + rt] = a;
        }
    }
}

// ---------------- launch 2: prep = gather + gsub + layer0 A/B + inits ----------------
__global__ void k_prep(const float* __restrict__ feat, const float* __restrict__ coor,
                       const float* __restrict__ We1, const float* __restrict__ be1){
    __shared__ float h[DIMF];
    int p, i, n; pool_of(blockIdx.x, p, i, n);
    const int* idx = g_idx + p*NFULL;
    int a = idx[i];
    int tid = threadIdx.x, lane = tid & 31;
    float s = g_scores[p*NFULL + a];
    if (tid < DIMF){
        float v = feat[a*DIMF + tid] * s;
        h[tid] = v;
        g_hc[p*NMAX*DIMF + i*DIMF + tid] = v;
    } else if (tid < DIMF + 3){
        int c = tid - DIMF;
        float cv = coor[a*3 + c];
        g_cA[p*NMAX*3 + i*3 + c] = cv;
        g_cB[p*NMAX*3 + i*3 + c] = cv;
    } else if (tid < DIMF + 3 + MD){
        g_mi[p*NMAX*MD + i*MD + (tid - DIMF - 3)] = 0.0f;
    } else if (tid >= 128){
        int w = (tid >> 5) - 4;
        for (int q = 0; q < 4; q++){
            int wd = w*4 + q, j = wd*32 + lane;
            bool bit = false;
            if (j < n){
                int gj = idx[j];
                bit = (g_ug2bits[a*16 + (gj>>5)] >> (gj&31)) & 1u;
            }
            unsigned m = __ballot_sync(0xffffffffu, bit);
            if (lane == 0) g_gsub[p*NMAX*16 + i*16 + wd] = m;
        }
    }
    __syncthreads();
    float* Ar = g_Arow + p*NMAX*H1 + i*H1;
    float* Br = g_Brow + p*NMAX*H1 + i*H1;
    for (int k = tid; k < H1; k += 256){
        float av = be1[k], bv = 0.0f;
        #pragma unroll
        for (int d = 0; d < DIMF; d++){
            av = fmaf(h[d], We1[d*H1 + k], av);
            bv = fmaf(h[d], We1[(DIMF + d)*H1 + k], bv);
        }
        Ar[k] = av;
        Br[k] = bv;
    }
}

// ---------------- launch 3: the heavy edge kernel (10 warps x 3 rows) ----------------
__global__ void __launch_bounds__(ETHR, 2) k_edge(int flag,
    const float* __restrict__ We1L, const float* __restrict__ We2L,
    const float* __restrict__ be2L, const float* __restrict__ Wc1L,
    const float* __restrict__ bc1L, const float* __restrict__ Wc2L,
    const float* __restrict__ bc2L)
{
    extern __shared__ float sm[];
    float* ws   = sm;               // 260*20: We2 k-rows, t-linear (17 used + 3 zero)
    float* Bs   = ws + 5200;        // 260*33: B tile, k-major, conflict-free
    float* As3  = Bs + 8580;        // 260*40: A tile, k-major, warp-quads (3 rows + pad)
    float* wded = As3 + 10400;      // 260*4: (wd,wd,we,we) -> one LDS.128
    float* wc1d = wded + 1040;      // 17*136: Wc1 duplicated pairs
    float* bc1d = wc1d + 2312;      // 136 (duplicated)
    float* wc2d = bc1d + 136;       // 136 (duplicated)
    float* be2p = wc2d + 136;       // 20 (t-linear, 17 used + 3 zero)
    float* cj   = be2p + 20;        // 96
    float* bc2s = cj + 96;          // 4  -> 27924 floats = 111696 B

    // pool decode
    int bid = blockIdx.x, p, lb, gx, nspl, n, nch;
    if (bid < 144){ p = 0; lb = bid;       gx = 16; nspl = 9; n = N0; nch = 15; }
    else if (bid < 228){ p = 1; lb = bid - 144; gx = 12; nspl = 7; n = N1; nch = 12; }
    else { p = 2; lb = bid - 228; gx = 11; nspl = 6; n = N2; nch = 10; }
    int bx = lb % gx, by = lb / gx;

    const float* Arow = g_Arow + p*NMAX*H1;
    const float* Brow = g_Brow + p*NMAX*H1;
    const uint32_t* gsub = g_gsub + p*NMAX*16;
    float* mi = g_mi + p*NMAX*MD;
    const float* ccur = (flag ? g_cB : g_cA) + p*NMAX*3;
    float*       cnext = (flag ? g_cA : g_cB) + p*NMAX*3;

    int tid = threadIdx.x, lane = tid & 31, wi = tid >> 5;
    const ull HALF2 = dup2(0.5f);

    // ---- stage weights ----
    for (int t = tid; t < 5200; t += ETHR){
        int k = t / 20, c = t - 20*k;
        ws[t] = (c < MD) ? We2L[k*MD + c] : 0.0f;
    }
    for (int t = tid; t < H1; t += ETHR){
        float wd = We1L[128*H1 + t], we = We1L[129*H1 + t];
        wded[4*t+0] = wd; wded[4*t+1] = wd; wded[4*t+2] = we; wded[4*t+3] = we;
    }
    for (int e = tid; e < MD*CHID; e += ETHR){
        int t = e / CHID, h = e - t*CHID;
        float v = Wc1L[e];
        wc1d[t*136 + 2*h] = v; wc1d[t*136 + 2*h + 1] = v;
    }
    if (tid < CHID){
        float v1 = bc1L[tid]; bc1d[2*tid] = v1; bc1d[2*tid+1] = v1;
        float v2 = Wc2L[tid]; wc2d[2*tid] = v2; wc2d[2*tid+1] = v2;
    }
    if (tid < 20) be2p[tid] = (tid < MD) ? be2L[tid] : 0.0f;
    if (tid == 0) bc2s[0] = bc2L[0];

    // ---- stage A tile (30 rows, 4-slot groups per warp) ----
    int i0 = bx * RPB;
    for (int e = tid; e < RPB*H1; e += ETHR){
        int r = e / H1, k = e - r*H1;
        int ii = i0 + r;
        As3[k*40 + 4*(r/3) + (r - 3*(r/3))] = (ii < n) ? Arow[ii*H1 + k] : 0.0f;
    }
    __syncthreads();
    const float bc2v = bc2s[0];

    int ia = i0 + 3*wi;
    bool iv0 = (ia < n), iv1 = (ia+1 < n), iv2 = (ia+2 < n);

    const ull* bc1u = (const ull*)bc1d;
    const ull* wc2u = (const ull*)wc2d;
    const ull* be2u = (const ull*)be2p;

    for (int ch = by; ch < nch; ch += nspl){
        int j0 = ch << 5;
        __syncthreads();
        for (int e = tid; e < 32*H1; e += ETHR){
            int jj = e / H1, k = e - jj*H1;
            int j = j0 + jj;
            Bs[k*33 + jj] = (j < n) ? Brow[j*H1 + k] : 0.0f;
        }
        for (int t = tid; t < 96; t += ETHR){
            int c = t / 32, jj = t - c*32;
            int j = j0 + jj;
            cj[t] = (j < n) ? ccur[j*3 + c] : 0.0f;
        }
        __syncthreads();
        if (!iv0) continue;   // staging/syncs above run unconditionally

        // coords reloaded per chunk (keeps k-loop register liveness low)
        float c0x = ccur[ia*3+0],  c0y = ccur[ia*3+1],  c0z = ccur[ia*3+2];
        float c1x = 0, c1y = 0, c1z = 0, c2x = 0, c2y = 0, c2z = 0;
        if (iv1){ c1x = ccur[(ia+1)*3+0]; c1y = ccur[(ia+1)*3+1]; c1z = ccur[(ia+1)*3+2]; }
        if (iv2){ c2x = ccur[(ia+2)*3+0]; c2y = ccur[(ia+2)*3+1]; c2z = ccur[(ia+2)*3+2]; }

        int j = j0 + lane;
        bool jv = (j < n);
        float jx = cj[lane], jy = cj[32+lane], jz = cj[64+lane];
        float r0x=c0x-jx, r0y=c0y-jy, r0z=c0z-jz;
        float r1x=c1x-jx, r1y=c1y-jy, r1z=c1z-jz;
        float r2x=c2x-jx, r2y=c2y-jy, r2z=c2z-jz;
        ull dd01 = pk2(r0x*r0x+r0y*r0y+r0z*r0z, r1x*r1x+r1y*r1y+r1z*r1z);
        float d2 = r2x*r2x + r2y*r2y + r2z*r2z;
        uint32_t gb0 = gsub[ia*16 + ch];
        uint32_t gb1 = iv1 ? gsub[(ia+1)*16 + ch] : 0u;
        uint32_t gb2 = iv2 ? gsub[(ia+2)*16 + ch] : 0u;
        ull ge01 = pk2(((gb0>>lane)&1u)?1.0f:0.0f, ((gb1>>lane)&1u)?1.0f:0.0f);
        float ge2 = ((gb2>>lane)&1u) ? 1.0f : 0.0f;

        // t-packed accumulators for 3 rows
        ull m0[9], m1[9], m2[9];
        #pragma unroll
        for (int tp = 0; tp < 9; tp++){
            ull b = be2u[tp];
            m0[tp] = b; m1[tp] = b; m2[tp] = b;
        }

        #pragma unroll 4
        for (int k = 0; k < H1; k++){
            float4 ap = *(const float4*)(As3 + k*40 + 4*wi);   // rows (0,1,2,pad)
            float4 wq = *(const float4*)(wded + (k<<2));       // (wd,wd,we,we)
            float bsv = Bs[k*33 + lane];
            // rows 0,1 packed
            ull pre = add2(pk2(ap.x, ap.y), dup2(bsv));
            pre = fma2(dd01, pk2(wq.x, wq.y), pre);            // reg-pair, no movs
            pre = fma2(ge01, pk2(wq.z, wq.w), pre);
            ull s01 = silu2t(pre, HALF2);
            // row 2 scalar
            float pre2 = ap.z + bsv;
            pre2 = fmaf(d2, wq.x, pre2);
            pre2 = fmaf(ge2, wq.z, pre2);
            float h2v = 0.5f * pre2;
            float s2 = fmaf(h2v, tanha(h2v), h2v);
            float s0, s1; unpk(s01, s0, s1);
            ull s0d = dup2(s0), s1d = dup2(s1), s2d = dup2(s2);
            const ulonglong2* q2 = (const ulonglong2*)(ws + k*20);
            #pragma unroll
            for (int pp = 0; pp < 4; pp++){
                ulonglong2 qq = q2[pp];
                m0[2*pp]   = fma2(s0d, qq.x, m0[2*pp]);
                m0[2*pp+1] = fma2(s0d, qq.y, m0[2*pp+1]);
                m1[2*pp]   = fma2(s1d, qq.x, m1[2*pp]);
                m1[2*pp+1] = fma2(s1d, qq.y, m1[2*pp+1]);
                m2[2*pp]   = fma2(s2d, qq.x, m2[2*pp]);
                m2[2*pp+1] = fma2(s2d, qq.y, m2[2*pp+1]);
            }
            {
                ull q8 = *(const ull*)(ws + k*20 + 16);
                m0[8] = fma2(s0d, q8, m0[8]);
                m1[8] = fma2(s1d, q8, m1[8]);
                m2[8] = fma2(s2d, q8, m2[8]);
            }
        }

        // convert: me01 = rows(0,1) packed; me22 = row2 self-duplicated
        ull me01[MD], me22[MD];
        #pragma unroll
        for (int tp = 0; tp < 9; tp++){
            float a0, a1, b0, b1, c0v, c1v;
            unpk(m0[tp], a0, a1); unpk(m1[tp], b0, b1); unpk(m2[tp], c0v, c1v);
            me01[2*tp] = silu2t(pk2(a0, b0), HALF2);
            me22[2*tp] = silu2t(dup2(c0v), HALF2);
            if (2*tp + 1 < MD){
                me01[2*tp+1] = silu2t(pk2(a1, b1), HALF2);
                me22[2*tp+1] = silu2t(dup2(c1v), HALF2);
            }
        }

        ull cw0d = dup2(bc2v);
        ull cw01 = coor_mlp2(me01, wc1d, bc1u, wc2u, cw0d, HALF2);
        ull cw22 = iv2 ? coor_mlp2(me22, wc1d, bc1u, wc2u, cw0d, HALF2) : cw0d;

        float mask = jv ? 1.0f : 0.0f;
        ull mask2 = dup2(mask);

        // m_i reduction
        #pragma unroll
        for (int t = 0; t < MD; t++){
            ull v = mul2(me01[t], mask2);
            v = add2(v, shflx2(v, 16)); v = add2(v, shflx2(v, 8));
            v = add2(v, shflx2(v, 4));  v = add2(v, shflx2(v, 2));
            v = add2(v, shflx2(v, 1));
            float w2 = 0.0f;
            { float wlo, whi; unpk(me22[t], wlo, whi); w2 = wlo * mask; }
            for (int off = 16; off; off >>= 1) w2 += __shfl_xor_sync(0xffffffffu, w2, off);
            if (lane == 0){
                float va, vb; unpk(v, va, vb);
                atomicAdd(&mi[ia*MD + t], va);
                if (iv1) atomicAdd(&mi[(ia+1)*MD + t], vb);
                if (iv2) atomicAdd(&mi[(ia+2)*MD + t], w2);
            }
        }

        // coor update reduction
        ull vx = mul2(mul2(cw01, pk2(r0x, r1x)), mask2);
        ull vy = mul2(mul2(cw01, pk2(r0y, r1y)), mask2);
        ull vz = mul2(mul2(cw01, pk2(r0z, r1z)), mask2);
        float cw2; { float lo, hi; unpk(cw22, lo, hi); cw2 = lo; }
        float wx = cw2*r2x*mask, wy = cw2*r2y*mask, wz = cw2*r2z*mask;
        #pragma unroll
        for (int off = 16; off; off >>= 1){
            vx = add2(vx, shflx2(vx, off));
            vy = add2(vy, shflx2(vy, off));
            vz = add2(vz, shflx2(vz, off));
            wx += __shfl_xor_sync(0xffffffffu, wx, off);
            wy += __shfl_xor_sync(0xffffffffu, wy, off);
            wz += __shfl_xor_sync(0xffffffffu, wz, off);
        }
        if (lane == 0){
            float xa,xb,ya,yb,za,zb;
            unpk(vx,xa,xb); unpk(vy,ya,yb); unpk(vz,za,zb);
            atomicAdd(&cnext[ia*3+0], xa); atomicAdd(&cnext[ia*3+1], ya); atomicAdd(&cnext[ia*3+2], za);
            if (iv1){ atomicAdd(&cnext[(ia+1)*3+0], xb); atomicAdd(&cnext[(ia+1)*3+1], yb); atomicAdd(&cnext[(ia+1)*3+2], zb); }
            if (iv2){ atomicAdd(&cnext[(ia+2)*3+0], wx); atomicAdd(&cnext[(ia+2)*3+1], wy); atomicAdd(&cnext[(ia+2)*3+2], wz); }
        }
    }
}

// ---------------- node MLP + next-layer A/B (all 3 pools) ----------------
__global__ void k_nodeAB(const float* __restrict__ Wn1L, const float* __restrict__ bn1L,
                         const float* __restrict__ Wn2L, const float* __restrict__ bn2L,
                         const float* __restrict__ We1N, const float* __restrict__ be1N,
                         int do_ab, int flag_next){
    __shared__ float in[81];
    __shared__ float z[128];
    __shared__ float hnew[DIMF];
    int p, i, n; pool_of(blockIdx.x, p, i, n);
    (void)n;
    int tid = threadIdx.x;
    float* hc = g_hc + p*NMAX*DIMF + i*DIMF;
    float* miP = g_mi + p*NMAX*MD + i*MD;
    if (tid < DIMF) in[tid] = hc[tid];
    else if (tid < 81) in[tid] = miP[tid - DIMF];
    __syncthreads();
    if (tid < 128){
        float acc = bn1L[tid];
        #pragma unroll 1
        for (int k = 0; k < 81; k++) acc = fmaf(in[k], Wn1L[k*128 + tid], acc);
        z[tid] = siluf(acc);
    }
    __syncthreads();
    if (tid < DIMF){
        float a2 = bn2L[tid];
        #pragma unroll 1
        for (int k = 0; k < 128; k++) a2 = fmaf(z[k], Wn2L[k*DIMF + tid], a2);
        float v = fmaxf(2.0f*in[tid] + a2, 0.0f);
        hnew[tid] = v;
        hc[tid] = v;
    }
    if (!do_ab) return;
    if (tid >= DIMF && tid < DIMF + MD) miP[tid - DIMF] = 0.0f;
    else if (tid >= DIMF + MD && tid < DIMF + MD + 3){
        int c = tid - DIMF - MD;
        float* cn = (flag_next ? g_cA : g_cB) + p*NMAX*3;
        const float* cc = (flag_next ? g_cB : g_cA) + p*NMAX*3;
        cn[i*3 + c] = cc[i*3 + c];
    }
    __syncthreads();
    float* Ar = g_Arow + p*NMAX*H1 + i*H1;
    float* Br = g_Brow + p*NMAX*H1 + i*H1;
    for (int k = tid; k < H1; k += 256){
        float a = be1N[k], b = 0.0f;
        #pragma unroll
        for (int d = 0; d < DIMF; d++){
            a = fmaf(hnew[d], We1N[d*H1 + k], a);
            b = fmaf(hnew[d], We1N[(DIMF + d)*H1 + k], b);
        }
        Ar[k] = a;
        Br[k] = b;
    }
}

// ---------------- final scatter with max-merge (values >= 0, out pre-zeroed) ----------------
__global__ void k_scatter(float* out){
    int p, i, n; pool_of(blockIdx.x, p, i, n);
    (void)n;
    int t = threadIdx.x;
    int a = g_idx[p*NFULL + i];
    float v = g_hc[p*NMAX*DIMF + i*DIMF + t];
    atomicMax((int*)&out[a*DIMF + t], __float_as_int(v));
}

// ---------------- host ----------------
extern "C" void kernel_launch(void* const* d_in, const int* in_sizes, int n_in,
                              void* d_out, int out_size){
    const float* feat = (const float*)d_in[0];
    const float* coor = (const float*)d_in[1];
    const float* edge = (const float*)d_in[2];
    const float* We1  = (const float*)d_in[3];
    const float* be1  = (const float*)d_in[4];
    const float* We2  = (const float*)d_in[5];
    const float* be2  = (const float*)d_in[6];
    const float* Wc1  = (const float*)d_in[7];
    const float* bc1  = (const float*)d_in[8];
    const float* Wc2  = (const float*)d_in[9];
    const float* bc2  = (const float*)d_in[10];
    const float* Wn1  = (const float*)d_in[11];
    const float* bn1  = (const float*)d_in[12];
    const float* Wn2  = (const float*)d_in[13];
    const float* bn2  = (const float*)d_in[14];
    const float* wp   = (const float*)d_in[15];
    const float* bp   = (const float*)d_in[16];
    float* out = (float*)d_out;

    const int EDGE_SMEM = 27924 * 4;   // 111696 B
    cudaFuncSetAttribute(k_edge, cudaFuncAttributeMaxDynamicSharedMemorySize, EDGE_SMEM);

    k_ugbits_scores<<<512, 512>>>(edge, feat, wp, bp);  // 0
    k_ug2rank<<<dim3(NFULL, 4), 128>>>(out);            // 1
    k_prep<<<NTOT, 256>>>(feat, coor, We1, be1);        // 2
    k_edge<<<EGRID, ETHR, EDGE_SMEM>>>(0,               // 3
        We1, We2, be2, Wc1, bc1, Wc2, bc2);
    k_nodeAB<<<NTOT, 256>>>(                            // 4
        Wn1, bn1, Wn2, bn2, We1 + 130*H1, be1 + H1, 1, 1);
    for (int l = 1; l < 3; l++){
        k_edge<<<EGRID, ETHR, EDGE_SMEM>>>(l & 1,       // 5, 7
            We1 + l*130*H1, We2 + l*H1*MD, be2 + l*MD,
            Wc1 + l*MD*CHID, bc1 + l*CHID, Wc2 + l*CHID, bc2 + l);
        int ln = (l < 2) ? (l + 1) : 2;
        k_nodeAB<<<NTOT, 256>>>(                        // 6, 8
            Wn1 + l*81*128, bn1 + l*128, Wn2 + l*128*DIMF, bn2 + l*DIMF,
            We1 + ln*130*H1, be1 + ln*H1,
            (l < 2) ? 1 : 0, (l + 1) & 1);
    }
    k_scatter<<<NTOT, 64>>>(out);                       // 9
}

// round 16
// speedup vs baseline: 1.1616x; 1.1616x over previous
#include <cuda_runtime.h>
#include <stdint.h>

#define NFULL 512
#define DIMF  64
#define H1    260
#define MD    17
#define CHID  68
#define NMAX  460
#define N0 460
#define N1 358
#define N2 307
#define NTOT 1125
#define EGRID 296  // one full wave at 2 blocks/SM
#define RPB   24   // rows per unit (12 warps x 2 rows)
#define ETHR  384
#define UNITS 610  // p0 20x15 + p1 15x12 + p2 13x10

typedef unsigned long long ull;

// ---------------- device scratch (per-pool batched) ----------------
__device__ uint32_t g_ugbits[NFULL*16];
__device__ uint32_t g_ug2bits[NFULL*16];
__device__ float    g_scores[3*NFULL];
__device__ int      g_idx[3*NFULL];
__device__ uint32_t g_gsub[3*NMAX*16];
__device__ float    g_hc[3*NMAX*DIMF];
__device__ float    g_cA[3*NMAX*3];
__device__ float    g_cB[3*NMAX*3];
__device__ float    g_Arow[3*NMAX*H1];
__device__ float    g_Brow[3*NMAX*H1];
__device__ float    g_mi[3*NMAX*MD];
__device__ unsigned g_uctr[3];   // dynamic work-queue counters (one per layer)

// ---------------- helpers ----------------
__device__ __forceinline__ float ex2a(float x){ float y; asm("ex2.approx.ftz.f32 %0, %1;" : "=f"(y) : "f"(x)); return y; }
__device__ __forceinline__ float rcpa(float x){ float y; asm("rcp.approx.ftz.f32 %0, %1;" : "=f"(y) : "f"(x)); return y; }
__device__ __forceinline__ float tanha(float x){ float y; asm("tanh.approx.f32 %0, %1;" : "=f"(y) : "f"(x)); return y; }
__device__ __forceinline__ float siluf(float x){
    return x * rcpa(1.0f + ex2a(-1.4426950408889634f * x));
}
__device__ __forceinline__ float sigf(float x){
    return rcpa(1.0f + ex2a(-1.4426950408889634f * x));
}
__device__ __forceinline__ ull pk2(float lo, float hi){
    ull r; asm("mov.b64 %0, {%1,%2};" : "=l"(r) : "r"(__float_as_uint(lo)), "r"(__float_as_uint(hi))); return r;
}
__device__ __forceinline__ ull dup2(float v){
    ull r; asm("mov.b64 %0, {%1,%1};" : "=l"(r) : "r"(__float_as_uint(v))); return r;
}
__device__ __forceinline__ void unpk(ull v, float& lo, float& hi){
    unsigned a, b;
    asm("mov.b64 {%0,%1}, %2;" : "=r"(a), "=r"(b) : "l"(v));
    lo = __uint_as_float(a); hi = __uint_as_float(b);
}
__device__ __forceinline__ ull fma2(ull a, ull b, ull c){
    ull d; asm("fma.rn.f32x2 %0, %1, %2, %3;" : "=l"(d) : "l"(a), "l"(b), "l"(c)); return d;
}
__device__ __forceinline__ ull add2(ull a, ull b){
    ull d; asm("add.rn.f32x2 %0, %1, %2;" : "=l"(d) : "l"(a), "l"(b)); return d;
}
__device__ __forceinline__ ull mul2(ull a, ull b){
    ull d; asm("mul.rn.f32x2 %0, %1, %2;" : "=l"(d) : "l"(a), "l"(b)); return d;
}
// packed silu via tanh: silu(x) = h + h*tanh(h), h = x/2  (rel_err ~3e-6)
__device__ __forceinline__ ull silu2t(ull x, ull HALF2){
    ull h = mul2(x, HALF2);
    float h0, h1; unpk(h, h0, h1);
    ull t = pk2(tanha(h0), tanha(h1));
    return fma2(h, t, h);
}
__device__ __forceinline__ ull shflx2(ull v, int off){
    float lo, hi; unpk(v, lo, hi);
    lo = __shfl_xor_sync(0xffffffffu, lo, off);
    hi = __shfl_xor_sync(0xffffffffu, hi, off);
    return pk2(lo, hi);
}
__device__ __forceinline__ void pool_of(int bid, int& p, int& i, int& n){
    if (bid < N0){ p = 0; i = bid; n = N0; }
    else if (bid < N0+N1){ p = 1; i = bid - N0; n = N1; }
    else { p = 2; i = bid - N0 - N1; n = N2; }
}

// ---------------- launch 0: adjacency bits + pool scores ----------------
__global__ void k_ugbits_scores(const float* __restrict__ edge, const float* __restrict__ feat,
                                const float* __restrict__ wp, const float* __restrict__ bp){
    int a = blockIdx.x, tid = threadIdx.x, lane = tid & 31, w = tid >> 5;
    bool b = edge[a*NFULL + tid] != 0.0f;
    unsigned m = __ballot_sync(0xffffffffu, b);
    if (lane == 0) g_ugbits[a*16 + w] = m;
    if (w < 3){
        float v = feat[a*DIMF + lane]*wp[w*DIMF + lane]
                + feat[a*DIMF + 32 + lane]*wp[w*DIMF + 32 + lane];
        for (int off = 16; off; off >>= 1) v += __shfl_xor_sync(0xffffffffu, v, off);
        if (lane == 0) g_scores[w*NFULL + a] = sigf(v + bp[w]);
    }
}

// ---------------- launch 1: fused ug2 (y=0, + zero out + ctr reset) + rank (y=1..3) ----------------
__global__ void k_ug2rank(float* out){
    int tid = threadIdx.x, lane = tid & 31, w = tid >> 5;
    int a = blockIdx.x;
    if (blockIdx.y == 0){
        if (tid < 64) out[a*64 + tid] = 0.0f;
        if (a == 0 && tid >= 64 && tid < 67) g_uctr[tid - 64] = 0u;
        __shared__ uint32_t row[16];
        __shared__ uint32_t accs[4][16];
        if (tid < 16) row[tid] = g_ugbits[a*16 + tid];
        __syncthreads();
        uint32_t acc = 0;
        int c0 = w*128;
        for (int c = c0; c < c0 + 128; c++){
            if ((row[c>>5] >> (c&31)) & 1u){
                if (lane < 16) acc |= g_ugbits[c*16 + lane];
            }
        }
        if (lane < 16) accs[w][lane] = acc;
        __syncthreads();
        if (tid < 16)
            g_ug2bits[a*16 + tid] = accs[0][tid] | accs[1][tid] | accs[2][tid] | accs[3][tid];
    } else {
        __shared__ int ired[4];
        int p = blockIdx.y - 1;
        int kcnt = (p == 0) ? N0 : (p == 1) ? N1 : N2;
        const float* sc = g_scores + p*NFULL;
        float s = sc[a];
        int r = 0;
        for (int b = tid; b < NFULL; b += 128){
            float sb = sc[b];
            r += (sb > s) || (sb == s && b < a);
        }
        for (int off = 16; off; off >>= 1) r += __shfl_xor_sync(0xffffffffu, r, off);
        if (lane == 0) ired[w] = r;
        __syncthreads();
        if (tid == 0){
            int rt = ired[0] + ired[1] + ired[2] + ired[3];
            if (rt < kcnt) g_idx[p*NFULL + rt] = a;
        }
    }
}

// ---------------- launch 2: prep = gather + gsub + layer0 A/B + inits ----------------
__global__ void k_prep(const float* __restrict__ feat, const float* __restrict__ coor,
                       const float* __restrict__ We1, const float* __restrict__ be1){
    __shared__ float h[DIMF];
    int p, i, n; pool_of(blockIdx.x, p, i, n);
    const int* idx = g_idx + p*NFULL;
    int a = idx[i];
    int tid = threadIdx.x, lane = tid & 31;
    float s = g_scores[p*NFULL + a];
    if (tid < DIMF){
        float v = feat[a*DIMF + tid] * s;
        h[tid] = v;
        g_hc[p*NMAX*DIMF + i*DIMF + tid] = v;
    } else if (tid < DIMF + 3){
        int c = tid - DIMF;
        float cv = coor[a*3 + c];
        g_cA[p*NMAX*3 + i*3 + c] = cv;
        g_cB[p*NMAX*3 + i*3 + c] = cv;
    } else if (tid < DIMF + 3 + MD){
        g_mi[p*NMAX*MD + i*MD + (tid - DIMF - 3)] = 0.0f;
    } else if (tid >= 128){
        int w = (tid >> 5) - 4;
        for (int q = 0; q < 4; q++){
            int wd = w*4 + q, j = wd*32 + lane;
            bool bit = false;
            if (j < n){
                int gj = idx[j];
                bit = (g_ug2bits[a*16 + (gj>>5)] >> (gj&31)) & 1u;
            }
            unsigned m = __ballot_sync(0xffffffffu, bit);
            if (lane == 0) g_gsub[p*NMAX*16 + i*16 + wd] = m;
        }
    }
    __syncthreads();
    float* Ar = g_Arow + p*NMAX*H1 + i*H1;
    float* Br = g_Brow + p*NMAX*H1 + i*H1;
    for (int k = tid; k < H1; k += 256){
        float av = be1[k], bv = 0.0f;
        #pragma unroll
        for (int d = 0; d < DIMF; d++){
            av = fmaf(h[d], We1[d*H1 + k], av);
            bv = fmaf(h[d], We1[(DIMF + d)*H1 + k], bv);
        }
        Ar[k] = av;
        Br[k] = bv;
    }
}

// ---------------- launch 3: the heavy edge kernel, DYNAMIC work queue ----------------
// 296 blocks x 384 thr; each block pulls units from g_uctr[lid] until exhausted.
// unit -> (pool, row-tile bx, j-chunk ch). Inner loop identical to R14 (best known).
__global__ void __launch_bounds__(ETHR, 2) k_edge(int flag, int lid,
    const float* __restrict__ We1L, const float* __restrict__ We2L,
    const float* __restrict__ be2L, const float* __restrict__ Wc1L,
    const float* __restrict__ bc1L, const float* __restrict__ Wc2L,
    const float* __restrict__ bc2L)
{
    extern __shared__ float sm[];
    float* ws   = sm;               // 260*20: We2 k-rows, t-linear (17 used + 3 zero)
    float* Bs   = ws + 5200;        // 260*33: B tile, k-major, conflict-free
    float* As2  = Bs + 8580;        // 260*24: A tile, k-major, 24 rows (even stride, LDS.64-safe)
    float* wded = As2 + 6240;       // 260*4: (wd,wd,we,we) -> one LDS.128
    float* wc1d = wded + 1040;      // 17*136: Wc1 duplicated pairs
    float* bc1d = wc1d + 2312;      // 136 (duplicated)
    float* wc2d = bc1d + 136;       // 136 (duplicated)
    float* be2p = wc2d + 136;       // 20 (t-linear, 17 used + 3 zero)
    float* cj   = be2p + 20;        // 96
    float* bc2s = cj + 96;          // 4  -> 23764 floats = 95056 B

    int tid = threadIdx.x, lane = tid & 31, wi = tid >> 5;
    const ull HALF2 = dup2(0.5f);

    // ---- stage layer weights once per block ----
    for (int t = tid; t < 5200; t += ETHR){
        int k = t / 20, c = t - 20*k;
        ws[t] = (c < MD) ? We2L[k*MD + c] : 0.0f;
    }
    for (int t = tid; t < H1; t += ETHR){
        float wd = We1L[128*H1 + t], we = We1L[129*H1 + t];
        wded[4*t+0] = wd; wded[4*t+1] = wd; wded[4*t+2] = we; wded[4*t+3] = we;
    }
    for (int e = tid; e < MD*CHID; e += ETHR){
        int t = e / CHID, h = e - t*CHID;
        float v = Wc1L[e];
        wc1d[t*136 + 2*h] = v; wc1d[t*136 + 2*h + 1] = v;
    }
    if (tid < CHID){
        float v1 = bc1L[tid]; bc1d[2*tid] = v1; bc1d[2*tid+1] = v1;
        float v2 = Wc2L[tid]; wc2d[2*tid] = v2; wc2d[2*tid+1] = v2;
    }
    if (tid < 20) be2p[tid] = (tid < MD) ? be2L[tid] : 0.0f;
    if (tid == 0) bc2s[0] = bc2L[0];

    const ull* bc1u = (const ull*)bc1d;
    const ull* wc2u = (const ull*)wc2d;
    const ull* be2u = (const ull*)be2p;

    __shared__ int s_u;
    for (;;){
        __syncthreads();   // prior unit's compute done; safe to restage & rewrite s_u
        if (tid == 0) s_u = (int)atomicAdd(&g_uctr[lid], 1u);
        __syncthreads();
        int u = s_u;
        if (u >= UNITS) break;

        // unit decode: pool, row-tile, chunk
        int p, bx, ch, n;
        if (u < 300){ p = 0; bx = u / 15; ch = u - bx*15; n = N0; }
        else if (u < 480){ int v = u - 300; p = 1; bx = v / 12; ch = v - bx*12; n = N1; }
        else { int v = u - 480; p = 2; bx = v / 10; ch = v - bx*10; n = N2; }

        const float* Arow = g_Arow + p*NMAX*H1;
        const float* Brow = g_Brow + p*NMAX*H1;
        const uint32_t* gsub = g_gsub + p*NMAX*16;
        float* mi = g_mi + p*NMAX*MD;
        const float* ccur = (flag ? g_cB : g_cA) + p*NMAX*3;
        float*       cnext = (flag ? g_cA : g_cB) + p*NMAX*3;

        int i0 = bx * RPB;
        int j0 = ch << 5;

        // ---- stage A tile + B tile + cj for this unit ----
        for (int e = tid; e < RPB*H1; e += ETHR){
            int r = e / H1, k = e - r*H1;
            int ii = i0 + r;
            As2[k*RPB + r] = (ii < n) ? Arow[ii*H1 + k] : 0.0f;
        }
        for (int e = tid; e < 32*H1; e += ETHR){
            int jj = e / H1, k = e - jj*H1;
            int j = j0 + jj;
            Bs[k*33 + jj] = (j < n) ? Brow[j*H1 + k] : 0.0f;
        }
        for (int t = tid; t < 96; t += ETHR){
            int c = t / 32, jj = t - c*32;
            int j = j0 + jj;
            cj[t] = (j < n) ? ccur[j*3 + c] : 0.0f;
        }
        __syncthreads();

        int ia = i0 + 2*wi, ib = ia + 1;
        bool iv0 = (ia < n), iv1 = (ib < n);
        if (!iv0) continue;   // no syncs below; loop top re-syncs

        float c0x = ccur[ia*3], c0y = ccur[ia*3+1], c0z = ccur[ia*3+2];
        float c1x = 0, c1y = 0, c1z = 0;
        if (iv1){ c1x = ccur[ib*3]; c1y = ccur[ib*3+1]; c1z = ccur[ib*3+2]; }

        int j = j0 + lane;
        bool jv = (j < n);
        float jx = cj[lane], jy = cj[32+lane], jz = cj[64+lane];
        float r0x=c0x-jx, r0y=c0y-jy, r0z=c0z-jz;
        float r1x=c1x-jx, r1y=c1y-jy, r1z=c1z-jz;
        ull dd01 = pk2(r0x*r0x+r0y*r0y+r0z*r0z, r1x*r1x+r1y*r1y+r1z*r1z);
        uint32_t gb0 = gsub[ia*16 + ch];
        uint32_t gb1 = iv1 ? gsub[ib*16 + ch] : 0u;
        ull ge01 = pk2(((gb0>>lane)&1u)?1.0f:0.0f, ((gb1>>lane)&1u)?1.0f:0.0f);

        // t-packed accumulators: m_a (row ia), m_b (row ib), 9 pairs each
        ull m_a[9], m_b[9];
        #pragma unroll
        for (int tp = 0; tp < 9; tp++){ m_a[tp] = be2u[tp]; m_b[tp] = m_a[tp]; }

        #pragma unroll 4
        for (int k = 0; k < H1; k++){
            ull ap = *(const ull*)(As2 + k*RPB + 2*wi);          // (A_ia, A_ib)
            ulonglong2 ww = *(const ulonglong2*)(wded + (k<<2)); // ((wd,wd),(we,we))
            ull bsvd = dup2(Bs[k*33 + lane]);
            ull pre = add2(ap, bsvd);
            pre = fma2(dd01, ww.x, pre);
            pre = fma2(ge01, ww.y, pre);
            ull s01 = silu2t(pre, HALF2);
            float s0, s1; unpk(s01, s0, s1);
            ull s0d = dup2(s0), s1d = dup2(s1);
            const ulonglong2* q2 = (const ulonglong2*)(ws + k*20);
            #pragma unroll
            for (int pp = 0; pp < 4; pp++){
                ulonglong2 qq = q2[pp];
                m_a[2*pp]   = fma2(s0d, qq.x, m_a[2*pp]);
                m_a[2*pp+1] = fma2(s0d, qq.y, m_a[2*pp+1]);
                m_b[2*pp]   = fma2(s1d, qq.x, m_b[2*pp]);
                m_b[2*pp+1] = fma2(s1d, qq.y, m_b[2*pp+1]);
            }
            {
                ull q8 = *(const ull*)(ws + k*20 + 16);
                m_a[8] = fma2(s0d, q8, m_a[8]);
                m_b[8] = fma2(s1d, q8, m_b[8]);
            }
        }

        // unpack t-pairs -> tanh silu -> repack as row-pairs me01[t] = (me_ia, me_ib)
        ull me01[MD];
        #pragma unroll
        for (int tp = 0; tp < 9; tp++){
            float a0, a1, b0, b1;
            unpk(m_a[tp], a0, a1); unpk(m_b[tp], b0, b1);
            me01[2*tp] = silu2t(pk2(a0, b0), HALF2);
            if (2*tp + 1 < MD) me01[2*tp+1] = silu2t(pk2(a1, b1), HALF2);
        }

        // coor MLP, row-pair packed, 2 hidden units per iter (tanh silu)
        ull cw01 = dup2(bc2s[0]);
        #pragma unroll 2
        for (int h2 = 0; h2 < CHID/2; h2++){
            ull a0 = bc1u[2*h2], a1 = bc1u[2*h2+1];
            #pragma unroll
            for (int t = 0; t < MD; t++){
                ulonglong2 wwp = ((const ulonglong2*)(wc1d + t*136))[h2];
                a0 = fma2(me01[t], wwp.x, a0);
                a1 = fma2(me01[t], wwp.y, a1);
            }
            a0 = silu2t(a0, HALF2); a1 = silu2t(a1, HALF2);
            cw01 = fma2(a0, wc2u[2*h2],   cw01);
            cw01 = fma2(a1, wc2u[2*h2+1], cw01);
        }

        float mask = jv ? 1.0f : 0.0f;
        ull mask2 = dup2(mask);

        // m_i reduction (row-pair packed)
        #pragma unroll
        for (int t = 0; t < MD; t++){
            ull v = mul2(me01[t], mask2);
            v = add2(v, shflx2(v, 16)); v = add2(v, shflx2(v, 8));
            v = add2(v, shflx2(v, 4));  v = add2(v, shflx2(v, 2));
            v = add2(v, shflx2(v, 1));
            if (lane == 0){
                float va, vb; unpk(v, va, vb);
                atomicAdd(&mi[ia*MD + t], va);
                if (iv1) atomicAdd(&mi[ib*MD + t], vb);
            }
        }

        // coor update reduction (row-pair packed)
        ull vx = mul2(mul2(cw01, pk2(r0x, r1x)), mask2);
        ull vy = mul2(mul2(cw01, pk2(r0y, r1y)), mask2);
        ull vz = mul2(mul2(cw01, pk2(r0z, r1z)), mask2);
        #pragma unroll
        for (int off = 16; off; off >>= 1){
            vx = add2(vx, shflx2(vx, off));
            vy = add2(vy, shflx2(vy, off));
            vz = add2(vz, shflx2(vz, off));
        }
        if (lane == 0){
            float xa,xb,ya,yb,za,zb;
            unpk(vx,xa,xb); unpk(vy,ya,yb); unpk(vz,za,zb);
            atomicAdd(&cnext[ia*3+0], xa); atomicAdd(&cnext[ia*3+1], ya); atomicAdd(&cnext[ia*3+2], za);
            if (iv1){ atomicAdd(&cnext[ib*3+0], xb); atomicAdd(&cnext[ib*3+1], yb); atomicAdd(&cnext[ib*3+2], zb); }
        }
    }
}

// ---------------- node MLP + next-layer A/B (all 3 pools) ----------------
__global__ void k_nodeAB(const float* __restrict__ Wn1L, const float* __restrict__ bn1L,
                         const float* __restrict__ Wn2L, const float* __restrict__ bn2L,
                         const float* __restrict__ We1N, const float* __restrict__ be1N,
                         int do_ab, int flag_next){
    __shared__ float in[81];
    __shared__ float z[128];
    __shared__ float hnew[DIMF];
    int p, i, n; pool_of(blockIdx.x, p, i, n);
    (void)n;
    int tid = threadIdx.x;
    float* hc = g_hc + p*NMAX*DIMF + i*DIMF;
    float* miP = g_mi + p*NMAX*MD + i*MD;
    if (tid < DIMF) in[tid] = hc[tid];
    else if (tid < 81) in[tid] = miP[tid - DIMF];
    __syncthreads();
    if (tid < 128){
        float acc = bn1L[tid];
        #pragma unroll 1
        for (int k = 0; k < 81; k++) acc = fmaf(in[k], Wn1L[k*128 + tid], acc);
        z[tid] = siluf(acc);
    }
    __syncthreads();
    if (tid < DIMF){
        float a2 = bn2L[tid];
        #pragma unroll 1
        for (int k = 0; k < 128; k++) a2 = fmaf(z[k], Wn2L[k*DIMF + tid], a2);
        float v = fmaxf(2.0f*in[tid] + a2, 0.0f);
        hnew[tid] = v;
        hc[tid] = v;
    }
    if (!do_ab) return;
    if (tid >= DIMF && tid < DIMF + MD) miP[tid - DIMF] = 0.0f;
    else if (tid >= DIMF + MD && tid < DIMF + MD + 3){
        int c = tid - DIMF - MD;
        float* cn = (flag_next ? g_cA : g_cB) + p*NMAX*3;
        const float* cc = (flag_next ? g_cB : g_cA) + p*NMAX*3;
        cn[i*3 + c] = cc[i*3 + c];
    }
    __syncthreads();
    float* Ar = g_Arow + p*NMAX*H1 + i*H1;
    float* Br = g_Brow + p*NMAX*H1 + i*H1;
    for (int k = tid; k < H1; k += 256){
        float a = be1N[k], b = 0.0f;
        #pragma unroll
        for (int d = 0; d < DIMF; d++){
            a = fmaf(hnew[d], We1N[d*H1 + k], a);
            b = fmaf(hnew[d], We1N[(DIMF + d)*H1 + k], b);
        }
        Ar[k] = a;
        Br[k] = b;
    }
}

// ---------------- final scatter with max-merge (values >= 0, out pre-zeroed) ----------------
__global__ void k_scatter(float* out){
    int p, i, n; pool_of(blockIdx.x, p, i, n);
    (void)n;
    int t = threadIdx.x;
    int a = g_idx[p*NFULL + i];
    float v = g_hc[p*NMAX*DIMF + i*DIMF + t];
    atomicMax((int*)&out[a*DIMF + t], __float_as_int(v));
}

// ---------------- host ----------------
extern "C" void kernel_launch(void* const* d_in, const int* in_sizes, int n_in,
                              void* d_out, int out_size){
    const float* feat = (const float*)d_in[0];
    const float* coor = (const float*)d_in[1];
    const float* edge = (const float*)d_in[2];
    const float* We1  = (const float*)d_in[3];
    const float* be1  = (const float*)d_in[4];
    const float* We2  = (const float*)d_in[5];
    const float* be2  = (const float*)d_in[6];
    const float* Wc1  = (const float*)d_in[7];
    const float* bc1  = (const float*)d_in[8];
    const float* Wc2  = (const float*)d_in[9];
    const float* bc2  = (const float*)d_in[10];
    const float* Wn1  = (const float*)d_in[11];
    const float* bn1  = (const float*)d_in[12];
    const float* Wn2  = (const float*)d_in[13];
    const float* bn2  = (const float*)d_in[14];
    const float* wp   = (const float*)d_in[15];
    const float* bp   = (const float*)d_in[16];
    float* out = (float*)d_out;

    const int EDGE_SMEM = 23764 * 4;   // 95056 B
    cudaFuncSetAttribute(k_edge, cudaFuncAttributeMaxDynamicSharedMemorySize, EDGE_SMEM);

    k_ugbits_scores<<<512, 512>>>(edge, feat, wp, bp);  // 0
    k_ug2rank<<<dim3(NFULL, 4), 128>>>(out);            // 1 (ug2 + rank + zero out + ctr reset)
    k_prep<<<NTOT, 256>>>(feat, coor, We1, be1);        // 2
    k_edge<<<EGRID, ETHR, EDGE_SMEM>>>(0, 0,            // 3  <- ncu capture slot
        We1, We2, be2, Wc1, bc1, Wc2, bc2);
    k_nodeAB<<<NTOT, 256>>>(                            // 4
        Wn1, bn1, Wn2, bn2, We1 + 130*H1, be1 + H1, 1, 1);
    for (int l = 1; l < 3; l++){
        k_edge<<<EGRID, ETHR, EDGE_SMEM>>>(l & 1, l,    // 5, 7
            We1 + l*130*H1, We2 + l*H1*MD, be2 + l*MD,
            Wc1 + l*MD*CHID, bc1 + l*CHID, Wc2 + l*CHID, bc2 + l);
        int ln = (l < 2) ? (l + 1) : 2;
        k_nodeAB<<<NTOT, 256>>>(                        // 6, 8
            Wn1 + l*81*128, bn1 + l*128, Wn2 + l*128*DIMF, bn2 + l*DIMF,
            We1 + ln*130*H1, be1 + ln*H1,
            (l < 2) ? 1 : 0, (l + 1) & 1);
    }
    k_scatter<<<NTOT, 64>>>(out);                       // 9
}

// round 17
// speedup vs baseline: 1.2540x; 1.0795x over previous
#include <cuda_runtime.h>
#include <stdint.h>

#define NFULL 512
#define DIMF  64
#define H1    260
#define MD    17
#define CHID  68
#define NMAX  460
#define N0 460
#define N1 358
#define N2 307
#define NTOT 1125
// edge grid: gx {20,15,13} x nspl {7,6,5} -> {140,90,65} = 295 blocks (one wave @2/SM)
#define EGRID 295
#define RPB   24   // rows per block (12 warps x 2 rows)
#define ETHR  384
#define ABNB  8    // nodes per k_ABn block
#define ABGRID ((NTOT + ABNB - 1) / ABNB)   // 141

typedef unsigned long long ull;

// ---------------- device scratch (per-pool batched) ----------------
__device__ uint32_t g_ugbits[NFULL*16];
__device__ uint32_t g_ug2bits[NFULL*16];
__device__ float    g_scores[3*NFULL];
__device__ int      g_idx[3*NFULL];
__device__ uint32_t g_gsub[3*NMAX*16];
__device__ float    g_hc[3*NMAX*DIMF];
__device__ float    g_cA[3*NMAX*3];
__device__ float    g_cB[3*NMAX*3];
__device__ float    g_Arow[3*NMAX*H1];
__device__ float    g_Brow[3*NMAX*H1];
__device__ float    g_mi[3*NMAX*MD];

// ---------------- helpers ----------------
__device__ __forceinline__ float ex2a(float x){ float y; asm("ex2.approx.ftz.f32 %0, %1;" : "=f"(y) : "f"(x)); return y; }
__device__ __forceinline__ float rcpa(float x){ float y; asm("rcp.approx.ftz.f32 %0, %1;" : "=f"(y) : "f"(x)); return y; }
__device__ __forceinline__ float tanha(float x){ float y; asm("tanh.approx.f32 %0, %1;" : "=f"(y) : "f"(x)); return y; }
__device__ __forceinline__ float siluf(float x){
    return x * rcpa(1.0f + ex2a(-1.4426950408889634f * x));
}
__device__ __forceinline__ float sigf(float x){
    return rcpa(1.0f + ex2a(-1.4426950408889634f * x));
}
__device__ __forceinline__ ull pk2(float lo, float hi){
    ull r; asm("mov.b64 %0, {%1,%2};" : "=l"(r) : "r"(__float_as_uint(lo)), "r"(__float_as_uint(hi))); return r;
}
__device__ __forceinline__ ull dup2(float v){
    ull r; asm("mov.b64 %0, {%1,%1};" : "=l"(r) : "r"(__float_as_uint(v))); return r;
}
__device__ __forceinline__ void unpk(ull v, float& lo, float& hi){
    unsigned a, b;
    asm("mov.b64 {%0,%1}, %2;" : "=r"(a), "=r"(b) : "l"(v));
    lo = __uint_as_float(a); hi = __uint_as_float(b);
}
__device__ __forceinline__ ull fma2(ull a, ull b, ull c){
    ull d; asm("fma.rn.f32x2 %0, %1, %2, %3;" : "=l"(d) : "l"(a), "l"(b), "l"(c)); return d;
}
__device__ __forceinline__ ull add2(ull a, ull b){
    ull d; asm("add.rn.f32x2 %0, %1, %2;" : "=l"(d) : "l"(a), "l"(b)); return d;
}
__device__ __forceinline__ ull mul2(ull a, ull b){
    ull d; asm("mul.rn.f32x2 %0, %1, %2;" : "=l"(d) : "l"(a), "l"(b)); return d;
}
// packed silu via tanh: silu(x) = h + h*tanh(h), h = x/2  (rel_err ~3e-6, verified)
__device__ __forceinline__ ull silu2t(ull x, ull HALF2){
    ull h = mul2(x, HALF2);
    float h0, h1; unpk(h, h0, h1);
    ull t = pk2(tanha(h0), tanha(h1));
    return fma2(h, t, h);
}
__device__ __forceinline__ ull shflx2(ull v, int off){
    float lo, hi; unpk(v, lo, hi);
    lo = __shfl_xor_sync(0xffffffffu, lo, off);
    hi = __shfl_xor_sync(0xffffffffu, hi, off);
    return pk2(lo, hi);
}
__device__ __forceinline__ void pool_of(int bid, int& p, int& i, int& n){
    if (bid < N0){ p = 0; i = bid; n = N0; }
    else if (bid < N0+N1){ p = 1; i = bid - N0; n = N1; }
    else { p = 2; i = bid - N0 - N1; n = N2; }
}

// ---------------- launch 0: adjacency bits + pool scores ----------------
__global__ void k_ugbits_scores(const float* __restrict__ edge, const float* __restrict__ feat,
                                const float* __restrict__ wp, const float* __restrict__ bp){
    int a = blockIdx.x, tid = threadIdx.x, lane = tid & 31, w = tid >> 5;
    bool b = edge[a*NFULL + tid] != 0.0f;
    unsigned m = __ballot_sync(0xffffffffu, b);
    if (lane == 0) g_ugbits[a*16 + w] = m;
    if (w < 3){
        float v = feat[a*DIMF + lane]*wp[w*DIMF + lane]
                + feat[a*DIMF + 32 + lane]*wp[w*DIMF + 32 + lane];
        for (int off = 16; off; off >>= 1) v += __shfl_xor_sync(0xffffffffu, v, off);
        if (lane == 0) g_scores[w*NFULL + a] = sigf(v + bp[w]);
    }
}

// ---------------- launch 1: fused ug2 (y=0, + zero out) + rank (y=1..3) ----------------
__global__ void k_ug2rank(float* out){
    int tid = threadIdx.x, lane = tid & 31, w = tid >> 5;
    int a = blockIdx.x;
    if (blockIdx.y == 0){
        if (tid < 64) out[a*64 + tid] = 0.0f;
        __shared__ uint32_t row[16];
        __shared__ uint32_t accs[4][16];
        if (tid < 16) row[tid] = g_ugbits[a*16 + tid];
        __syncthreads();
        uint32_t acc = 0;
        int c0 = w*128;
        for (int c = c0; c < c0 + 128; c++){
            if ((row[c>>5] >> (c&31)) & 1u){
                if (lane < 16) acc |= g_ugbits[c*16 + lane];
            }
        }
        if (lane < 16) accs[w][lane] = acc;
        __syncthreads();
        if (tid < 16)
            g_ug2bits[a*16 + tid] = accs[0][tid] | accs[1][tid] | accs[2][tid] | accs[3][tid];
    } else {
        __shared__ int ired[4];
        int p = blockIdx.y - 1;
        int kcnt = (p == 0) ? N0 : (p == 1) ? N1 : N2;
        const float* sc = g_scores + p*NFULL;
        float s = sc[a];
        int r = 0;
        for (int b = tid; b < NFULL; b += 128){
            float sb = sc[b];
            r += (sb > s) || (sb == s && b < a);
        }
        for (int off = 16; off; off >>= 1) r += __shfl_xor_sync(0xffffffffu, r, off);
        if (lane == 0) ired[w] = r;
        __syncthreads();
        if (tid == 0){
            int rt = ired[0] + ired[1] + ired[2] + ired[3];
            if (rt < kcnt) g_idx[p*NFULL + rt] = a;
        }
    }
}

// ---------------- launch 2: prep = gather + gsub (A/B + inits moved to k_ABn) ----------------
__global__ void k_prep(const float* __restrict__ feat, const float* __restrict__ coor){
    int p, i, n; pool_of(blockIdx.x, p, i, n);
    const int* idx = g_idx + p*NFULL;
    int a = idx[i];
    int tid = threadIdx.x, lane = tid & 31;
    if (tid < DIMF){
        float s = g_scores[p*NFULL + a];
        g_hc[p*NMAX*DIMF + i*DIMF + tid] = feat[a*DIMF + tid] * s;
    } else if (tid < DIMF + 3){
        int c = tid - DIMF;
        g_cA[p*NMAX*3 + i*3 + c] = coor[a*3 + c];
    } else if (tid >= 128){
        int w = (tid >> 5) - 4;
        for (int q = 0; q < 4; q++){
            int wd = w*4 + q, j = wd*32 + lane;
            bool bit = false;
            if (j < n){
                int gj = idx[j];
                bit = (g_ug2bits[a*16 + (gj>>5)] >> (gj&31)) & 1u;
            }
            unsigned m = __ballot_sync(0xffffffffu, bit);
            if (lane == 0) g_gsub[p*NMAX*16 + i*16 + wd] = m;
        }
    }
}

// ---------------- k_ABn: batched A/B GEMM (8 nodes/block) + mi zero + coor init ----------------
// A = h@We1[0:64] + be1, B = h@We1[64:128]; We1 read ONCE per 8 nodes (L2 traffic /8).
__global__ void k_ABn(int fl, const float* __restrict__ We1L, const float* __restrict__ be1L){
    __shared__ float hT[DIMF*ABNB];   // transposed: hT[d*8 + s]
    int tid = threadIdx.x;
    int s0 = blockIdx.x * ABNB;

    // stage h transposed + zero mi + init coor
    for (int e = tid; e < ABNB*DIMF; e += 256){
        int s = e >> 6, d = e & 63;
        int slot = s0 + s;
        float v = 0.0f;
        if (slot < NTOT){
            int p, i, n; pool_of(slot, p, i, n);
            v = g_hc[p*NMAX*DIMF + i*DIMF + d];
        }
        hT[d*ABNB + s] = v;
    }
    for (int e = tid; e < ABNB*MD; e += 256){
        int s = e / MD, t = e - s*MD;
        int slot = s0 + s;
        if (slot < NTOT){
            int p, i, n; pool_of(slot, p, i, n);
            g_mi[p*NMAX*MD + i*MD + t] = 0.0f;
        }
    }
    if (tid < ABNB*3){
        int s = tid / 3, c = tid - 3*s;
        int slot = s0 + s;
        if (slot < NTOT){
            int p, i, n; pool_of(slot, p, i, n);
            const float* cc = (fl ? g_cB : g_cA) + p*NMAX*3;
            float*       cn = (fl ? g_cA : g_cB) + p*NMAX*3;
            cn[i*3 + c] = cc[i*3 + c];
        }
    }
    __syncthreads();

    for (int k = tid; k < H1; k += 256){
        float a[ABNB], b[ABNB];
        float be = be1L[k];
        #pragma unroll
        for (int s = 0; s < ABNB; s++){ a[s] = be; b[s] = 0.0f; }
        #pragma unroll 4
        for (int d = 0; d < DIMF; d++){
            float w1 = We1L[d*H1 + k];
            float w2 = We1L[(DIMF + d)*H1 + k];
            float4 h0 = *(const float4*)(hT + d*ABNB);
            float4 h1 = *(const float4*)(hT + d*ABNB + 4);
            a[0] = fmaf(h0.x, w1, a[0]); b[0] = fmaf(h0.x, w2, b[0]);
            a[1] = fmaf(h0.y, w1, a[1]); b[1] = fmaf(h0.y, w2, b[1]);
            a[2] = fmaf(h0.z, w1, a[2]); b[2] = fmaf(h0.z, w2, b[2]);
            a[3] = fmaf(h0.w, w1, a[3]); b[3] = fmaf(h0.w, w2, b[3]);
            a[4] = fmaf(h1.x, w1, a[4]); b[4] = fmaf(h1.x, w2, b[4]);
            a[5] = fmaf(h1.y, w1, a[5]); b[5] = fmaf(h1.y, w2, b[5]);
            a[6] = fmaf(h1.z, w1, a[6]); b[6] = fmaf(h1.z, w2, b[6]);
            a[7] = fmaf(h1.w, w1, a[7]); b[7] = fmaf(h1.w, w2, b[7]);
        }
        #pragma unroll
        for (int s = 0; s < ABNB; s++){
            int slot = s0 + s;
            if (slot < NTOT){
                int p, i, n; pool_of(slot, p, i, n);
                g_Arow[p*NMAX*H1 + i*H1 + k] = a[s];
                g_Brow[p*NMAX*H1 + i*H1 + k] = b[s];
            }
        }
    }
}

// ---------------- the heavy edge kernel (EXACT R14: 12 warps x 2 rows, static grid) ----------------
__global__ void __launch_bounds__(ETHR, 2) k_edge(int flag,
    const float* __restrict__ We1L, const float* __restrict__ We2L,
    const float* __restrict__ be2L, const float* __restrict__ Wc1L,
    const float* __restrict__ bc1L, const float* __restrict__ Wc2L,
    const float* __restrict__ bc2L)
{
    extern __shared__ float sm[];
    float* ws   = sm;               // 260*20
    float* Bs   = ws + 5200;        // 260*33
    float* As2  = Bs + 8580;        // 260*24
    float* wded = As2 + 6240;       // 260*4
    float* wc1d = wded + 1040;      // 17*136
    float* bc1d = wc1d + 2312;      // 136
    float* wc2d = bc1d + 136;       // 136
    float* be2p = wc2d + 136;       // 20
    float* cj   = be2p + 20;        // 96
    float* bc2s = cj + 96;          // 4  -> 23764 floats = 95056 B

    int bid = blockIdx.x, p, lb, gx, nspl, n, nch;
    if (bid < 140){ p = 0; lb = bid;       gx = 20; nspl = 7; n = N0; nch = 15; }
    else if (bid < 230){ p = 1; lb = bid - 140; gx = 15; nspl = 6; n = N1; nch = 12; }
    else { p = 2; lb = bid - 230; gx = 13; nspl = 5; n = N2; nch = 10; }
    int bx = lb % gx, by = lb / gx;

    const float* Arow = g_Arow + p*NMAX*H1;
    const float* Brow = g_Brow + p*NMAX*H1;
    const uint32_t* gsub = g_gsub + p*NMAX*16;
    float* mi = g_mi + p*NMAX*MD;
    const float* ccur = (flag ? g_cB : g_cA) + p*NMAX*3;
    float*       cnext = (flag ? g_cA : g_cB) + p*NMAX*3;

    int tid = threadIdx.x, lane = tid & 31, wi = tid >> 5;
    const ull HALF2 = dup2(0.5f);

    for (int t = tid; t < 5200; t += ETHR){
        int k = t / 20, c = t - 20*k;
        ws[t] = (c < MD) ? We2L[k*MD + c] : 0.0f;
    }
    for (int t = tid; t < H1; t += ETHR){
        float wd = We1L[128*H1 + t], we = We1L[129*H1 + t];
        wded[4*t+0] = wd; wded[4*t+1] = wd; wded[4*t+2] = we; wded[4*t+3] = we;
    }
    for (int e = tid; e < MD*CHID; e += ETHR){
        int t = e / CHID, h = e - t*CHID;
        float v = Wc1L[e];
        wc1d[t*136 + 2*h] = v; wc1d[t*136 + 2*h + 1] = v;
    }
    if (tid < CHID){
        float v1 = bc1L[tid]; bc1d[2*tid] = v1; bc1d[2*tid+1] = v1;
        float v2 = Wc2L[tid]; wc2d[2*tid] = v2; wc2d[2*tid+1] = v2;
    }
    if (tid < 20) be2p[tid] = (tid < MD) ? be2L[tid] : 0.0f;
    if (tid == 0) bc2s[0] = bc2L[0];

    int i0 = bx * RPB;
    for (int e = tid; e < RPB*H1; e += ETHR){
        int r = e / H1, k = e - r*H1;
        int ii = i0 + r;
        As2[k*RPB + r] = (ii < n) ? Arow[ii*H1 + k] : 0.0f;
    }
    __syncthreads();
    const float bc2v = bc2s[0];

    int ia = i0 + 2*wi, ib = ia + 1;
    bool iv0 = (ia < n), iv1 = (ib < n);
    float c0x=0,c0y=0,c0z=0,c1x=0,c1y=0,c1z=0;
    if (iv0){ c0x=ccur[ia*3];  c0y=ccur[ia*3+1];  c0z=ccur[ia*3+2]; }
    if (iv1){ c1x=ccur[ib*3];  c1y=ccur[ib*3+1];  c1z=ccur[ib*3+2]; }

    const ull* bc1u = (const ull*)bc1d;
    const ull* wc2u = (const ull*)wc2d;
    const ull* be2u = (const ull*)be2p;

    for (int ch = by; ch < nch; ch += nspl){
        int j0 = ch << 5;
        __syncthreads();
        for (int e = tid; e < 32*H1; e += ETHR){
            int jj = e / H1, k = e - jj*H1;
            int j = j0 + jj;
            Bs[k*33 + jj] = (j < n) ? Brow[j*H1 + k] : 0.0f;
        }
        for (int t = tid; t < 96; t += ETHR){
            int c = t / 32, jj = t - c*32;
            int j = j0 + jj;
            cj[t] = (j < n) ? ccur[j*3 + c] : 0.0f;
        }
        __syncthreads();
        if (!iv0) continue;

        int j = j0 + lane;
        bool jv = (j < n);
        float jx = cj[lane], jy = cj[32+lane], jz = cj[64+lane];
        float r0x=c0x-jx, r0y=c0y-jy, r0z=c0z-jz;
        float r1x=c1x-jx, r1y=c1y-jy, r1z=c1z-jz;
        ull dd01 = pk2(r0x*r0x+r0y*r0y+r0z*r0z, r1x*r1x+r1y*r1y+r1z*r1z);
        uint32_t gb0 = iv0 ? gsub[ia*16 + ch] : 0u;
        uint32_t gb1 = iv1 ? gsub[ib*16 + ch] : 0u;
        ull ge01 = pk2(((gb0>>lane)&1u)?1.0f:0.0f, ((gb1>>lane)&1u)?1.0f:0.0f);

        ull m_a[9], m_b[9];
        #pragma unroll
        for (int tp = 0; tp < 9; tp++){ m_a[tp] = be2u[tp]; m_b[tp] = m_a[tp]; }

        #pragma unroll 4
        for (int k = 0; k < H1; k++){
            ull ap = *(const ull*)(As2 + k*RPB + 2*wi);
            ulonglong2 ww = *(const ulonglong2*)(wded + (k<<2));
            ull bsvd = dup2(Bs[k*33 + lane]);
            ull pre = add2(ap, bsvd);
            pre = fma2(dd01, ww.x, pre);
            pre = fma2(ge01, ww.y, pre);
            ull s01 = silu2t(pre, HALF2);
            float s0, s1; unpk(s01, s0, s1);
            ull s0d = dup2(s0), s1d = dup2(s1);
            const ulonglong2* q2 = (const ulonglong2*)(ws + k*20);
            #pragma unroll
            for (int pp = 0; pp < 4; pp++){
                ulonglong2 qq = q2[pp];
                m_a[2*pp]   = fma2(s0d, qq.x, m_a[2*pp]);
                m_a[2*pp+1] = fma2(s0d, qq.y, m_a[2*pp+1]);
                m_b[2*pp]   = fma2(s1d, qq.x, m_b[2*pp]);
                m_b[2*pp+1] = fma2(s1d, qq.y, m_b[2*pp+1]);
            }
            {
                ull q8 = *(const ull*)(ws + k*20 + 16);
                m_a[8] = fma2(s0d, q8, m_a[8]);
                m_b[8] = fma2(s1d, q8, m_b[8]);
            }
        }

        ull me01[MD];
        #pragma unroll
        for (int tp = 0; tp < 9; tp++){
            float a0, a1, b0, b1;
            unpk(m_a[tp], a0, a1); unpk(m_b[tp], b0, b1);
            me01[2*tp] = silu2t(pk2(a0, b0), HALF2);
            if (2*tp + 1 < MD) me01[2*tp+1] = silu2t(pk2(a1, b1), HALF2);
        }

        ull cw01 = dup2(bc2v);
        #pragma unroll 2
        for (int h2 = 0; h2 < CHID/2; h2++){
            ull a0 = bc1u[2*h2], a1 = bc1u[2*h2+1];
            #pragma unroll
            for (int t = 0; t < MD; t++){
                ulonglong2 wwp = ((const ulonglong2*)(wc1d + t*136))[h2];
                a0 = fma2(me01[t], wwp.x, a0);
                a1 = fma2(me01[t], wwp.y, a1);
            }
            a0 = silu2t(a0, HALF2); a1 = silu2t(a1, HALF2);
            cw01 = fma2(a0, wc2u[2*h2],   cw01);
            cw01 = fma2(a1, wc2u[2*h2+1], cw01);
        }

        float mask = jv ? 1.0f : 0.0f;
        ull mask2 = dup2(mask);

        #pragma unroll
        for (int t = 0; t < MD; t++){
            ull v = mul2(me01[t], mask2);
            v = add2(v, shflx2(v, 16)); v = add2(v, shflx2(v, 8));
            v = add2(v, shflx2(v, 4));  v = add2(v, shflx2(v, 2));
            v = add2(v, shflx2(v, 1));
            if (lane == 0){
                float va, vb; unpk(v, va, vb);
                atomicAdd(&mi[ia*MD + t], va);
                if (iv1) atomicAdd(&mi[ib*MD + t], vb);
            }
        }

        ull vx = mul2(mul2(cw01, pk2(r0x, r1x)), mask2);
        ull vy = mul2(mul2(cw01, pk2(r0y, r1y)), mask2);
        ull vz = mul2(mul2(cw01, pk2(r0z, r1z)), mask2);
        #pragma unroll
        for (int off = 16; off; off >>= 1){
            vx = add2(vx, shflx2(vx, off));
            vy = add2(vy, shflx2(vy, off));
            vz = add2(vz, shflx2(vz, off));
        }
        if (lane == 0){
            float xa,xb,ya,yb,za,zb;
            unpk(vx,xa,xb); unpk(vy,ya,yb); unpk(vz,za,zb);
            atomicAdd(&cnext[ia*3+0], xa); atomicAdd(&cnext[ia*3+1], ya); atomicAdd(&cnext[ia*3+2], za);
            if (iv1){ atomicAdd(&cnext[ib*3+0], xb); atomicAdd(&cnext[ib*3+1], yb); atomicAdd(&cnext[ib*3+2], zb); }
        }
    }
}

// ---------------- node MLP only: hc = relu(2*hc + MLP([hc, m_i])) ----------------
__global__ void k_node(const float* __restrict__ Wn1L, const float* __restrict__ bn1L,
                       const float* __restrict__ Wn2L, const float* __restrict__ bn2L){
    __shared__ float in[81];
    __shared__ float z[128];
    int p, i, n; pool_of(blockIdx.x, p, i, n);
    (void)n;
    int tid = threadIdx.x;
    float* hc = g_hc + p*NMAX*DIMF + i*DIMF;
    const float* miP = g_mi + p*NMAX*MD + i*MD;
    if (tid < DIMF) in[tid] = hc[tid];
    else if (tid < 81) in[tid] = miP[tid - DIMF];
    __syncthreads();
    float acc = bn1L[tid];
    #pragma unroll 1
    for (int k = 0; k < 81; k++) acc = fmaf(in[k], Wn1L[k*128 + tid], acc);
    z[tid] = siluf(acc);
    __syncthreads();
    if (tid < DIMF){
        float a2 = bn2L[tid];
        #pragma unroll 1
        for (int k = 0; k < 128; k++) a2 = fmaf(z[k], Wn2L[k*DIMF + tid], a2);
        hc[tid] = fmaxf(2.0f*in[tid] + a2, 0.0f);
    }
}

// ---------------- final scatter with max-merge (values >= 0, out pre-zeroed) ----------------
__global__ void k_scatter(float* out){
    int p, i, n; pool_of(blockIdx.x, p, i, n);
    (void)n;
    int t = threadIdx.x;
    int a = g_idx[p*NFULL + i];
    float v = g_hc[p*NMAX*DIMF + i*DIMF + t];
    atomicMax((int*)&out[a*DIMF + t], __float_as_int(v));
}

// ---------------- host ----------------
extern "C" void kernel_launch(void* const* d_in, const int* in_sizes, int n_in,
                              void* d_out, int out_size){
    const float* feat = (const float*)d_in[0];
    const float* coor = (const float*)d_in[1];
    const float* edge = (const float*)d_in[2];
    const float* We1  = (const float*)d_in[3];
    const float* be1  = (const float*)d_in[4];
    const float* We2  = (const float*)d_in[5];
    const float* be2  = (const float*)d_in[6];
    const float* Wc1  = (const float*)d_in[7];
    const float* bc1  = (const float*)d_in[8];
    const float* Wc2  = (const float*)d_in[9];
    const float* bc2  = (const float*)d_in[10];
    const float* Wn1  = (const float*)d_in[11];
    const float* bn1  = (const float*)d_in[12];
    const float* Wn2  = (const float*)d_in[13];
    const float* bn2  = (const float*)d_in[14];
    const float* wp   = (const float*)d_in[15];
    const float* bp   = (const float*)d_in[16];
    float* out = (float*)d_out;

    const int EDGE_SMEM = 23764 * 4;   // 95056 B
    cudaFuncSetAttribute(k_edge, cudaFuncAttributeMaxDynamicSharedMemorySize, EDGE_SMEM);

    k_ugbits_scores<<<512, 512>>>(edge, feat, wp, bp);  // 0
    k_ug2rank<<<dim3(NFULL, 4), 128>>>(out);            // 1
    k_prep<<<NTOT, 256>>>(feat, coor);                  // 2
    for (int l = 0; l < 3; l++){
        k_ABn<<<ABGRID, 256>>>(l & 1, We1 + l*130*H1, be1 + l*H1);  // 3, 7, 11
        k_edge<<<EGRID, ETHR, EDGE_SMEM>>>(l & 1,                    // 4, 8, 12
            We1 + l*130*H1, We2 + l*H1*MD, be2 + l*MD,
            Wc1 + l*MD*CHID, bc1 + l*CHID, Wc2 + l*CHID, bc2 + l);
        k_node<<<NTOT, 128>>>(                                       // 5, 9, 13
            Wn1 + l*81*128, bn1 + l*128, Wn2 + l*128*DIMF, bn2 + l*DIMF);
    }
    k_scatter<<<NTOT, 64>>>(out);
}